// round 1
// baseline (speedup 1.0000x reference)
#include <cuda_runtime.h>
#include <cstdint>
#include <cstddef>

#define B_SZ 256
#define NTOK 196
#define C_DIM 512
#define NH 8
#define KD 32
#define DV 128
#define DH 1024
#define HQKV 1536
#define QT 49
#define SCALE 0.17677669529663687f

// Scratch buffers (device globals: allocation-free rule)
__device__ float g_qkv[(size_t)B_SZ * NTOK * HQKV];   // [B, N, 1536]
__device__ float g_att[(size_t)B_SZ * NTOK * DH];     // [B, N, 1024]

// ---------------------------------------------------------------------------
// Generic C[M,N] = A[M,K] @ W[N,K]^T + bias[N]
// 128x128 block tile, BK=16, 8x8 per-thread microtile, 256 threads.
// M % 128 == 0, N % 128 == 0, K % 16 == 0 hold for both uses (no guards).
// ---------------------------------------------------------------------------
__global__ void __launch_bounds__(256, 2)
gemm_tn_bias(const float* __restrict__ A, const float* __restrict__ W,
             const float* __restrict__ bias, float* __restrict__ C,
             int M, int N, int K)
{
    __shared__ float As[16 * 132];   // [k][m], padded pitch 132
    __shared__ float Bs[16 * 132];   // [k][n]

    const int tid = threadIdx.x;
    const int tm = tid >> 4;         // 0..15
    const int tn = tid & 15;         // 0..15
    const int m0 = blockIdx.y * 128;
    const int n0 = blockIdx.x * 128;

    float acc[8][8];
    #pragma unroll
    for (int i = 0; i < 8; i++)
        #pragma unroll
        for (int j = 0; j < 8; j++) acc[i][j] = 0.f;

    for (int kk = 0; kk < K; kk += 16) {
        #pragma unroll
        for (int it = 0; it < 2; it++) {
            int i = tid + it * 256;          // 0..511 float4 slots
            int row = i >> 2;                // 0..127
            int kc  = (i & 3) << 2;          // 0,4,8,12
            float4 av = *(const float4*)(A + (size_t)(m0 + row) * K + kk + kc);
            float4 wv = *(const float4*)(W + (size_t)(n0 + row) * K + kk + kc);
            As[(kc + 0) * 132 + row] = av.x;
            As[(kc + 1) * 132 + row] = av.y;
            As[(kc + 2) * 132 + row] = av.z;
            As[(kc + 3) * 132 + row] = av.w;
            Bs[(kc + 0) * 132 + row] = wv.x;
            Bs[(kc + 1) * 132 + row] = wv.y;
            Bs[(kc + 2) * 132 + row] = wv.z;
            Bs[(kc + 3) * 132 + row] = wv.w;
        }
        __syncthreads();
        #pragma unroll
        for (int k = 0; k < 16; k++) {
            float4 a0 = *(const float4*)(As + k * 132 + tm * 8);
            float4 a1 = *(const float4*)(As + k * 132 + tm * 8 + 4);
            float4 b0 = *(const float4*)(Bs + k * 132 + tn * 8);
            float4 b1 = *(const float4*)(Bs + k * 132 + tn * 8 + 4);
            float a[8] = {a0.x, a0.y, a0.z, a0.w, a1.x, a1.y, a1.z, a1.w};
            float b[8] = {b0.x, b0.y, b0.z, b0.w, b1.x, b1.y, b1.z, b1.w};
            #pragma unroll
            for (int i = 0; i < 8; i++)
                #pragma unroll
                for (int j = 0; j < 8; j++)
                    acc[i][j] += a[i] * b[j];
        }
        __syncthreads();
    }

    float bb[8];
    #pragma unroll
    for (int j = 0; j < 8; j++) bb[j] = bias[n0 + tn * 8 + j];
    #pragma unroll
    for (int i = 0; i < 8; i++) {
        float* cp = C + (size_t)(m0 + tm * 8 + i) * N + n0 + tn * 8;
        float4 o0 = make_float4(acc[i][0] + bb[0], acc[i][1] + bb[1],
                                acc[i][2] + bb[2], acc[i][3] + bb[3]);
        float4 o1 = make_float4(acc[i][4] + bb[4], acc[i][5] + bb[5],
                                acc[i][6] + bb[6], acc[i][7] + bb[7]);
        *(float4*)cp = o0;
        *(float4*)(cp + 4) = o1;
    }
}

// ---------------------------------------------------------------------------
// Attention: one CTA per (qtile of 49 queries, head, batch). 256 threads.
// S = qK^T (smem), softmax(S*scale + bias) in-place, O = P V.
// ---------------------------------------------------------------------------
__global__ void __launch_bounds__(256)
attn_kernel(const float* __restrict__ qkv, const float* __restrict__ biases,
            const int* __restrict__ bidx, float* __restrict__ attn_out, int n_off)
{
    extern __shared__ float sm[];
    float* sq = sm;                 // [64][33]  = 2112 floats (rows 49..63 zero)
    float* sk = sm + 2112;          // [196][33] = 6468
    float* sS = sm + 8580;          // [64][197] = 12608
    float* sv = sm + 21188;         // [49][128] = 6272   (total 27460 floats)

    const int tid  = threadIdx.x;
    const int lane = tid & 31;
    const int wid  = tid >> 5;
    const int qt = blockIdx.x;
    const int h  = blockIdx.y;
    const int b  = blockIdx.z;
    const float* base = qkv + (size_t)b * NTOK * HQKV + h * (2 * KD + DV);

    // ---- load Q tile [49][32] ----
    for (int i = tid; i < QT * 8; i += 256) {
        int r = i >> 3, c = (i & 7) << 2;
        float4 v = *(const float4*)(base + (size_t)(qt * QT + r) * HQKV + c);
        float* d = sq + r * 33 + c;
        d[0] = v.x; d[1] = v.y; d[2] = v.z; d[3] = v.w;
    }
    for (int i = tid; i < 15 * 33; i += 256) sq[49 * 33 + i] = 0.f;
    // ---- load K [196][32] ----
    for (int i = tid; i < NTOK * 8; i += 256) {
        int r = i >> 3, c = (i & 7) << 2;
        float4 v = *(const float4*)(base + (size_t)r * HQKV + KD + c);
        float* d = sk + r * 33 + c;
        d[0] = v.x; d[1] = v.y; d[2] = v.z; d[3] = v.w;
    }
    __syncthreads();

    // ---- S = q K^T : warp tiles 16x32, lane microtile 4x4 ----
    const int qil = (lane & 3) << 2;   // 0,4,8,12
    const int kjl = (lane >> 2) << 2;  // 0..28
    for (int wt = wid; wt < 28; wt += 8) {
        int qi0 = (wt / 7) * 16 + qil;
        int kj0 = (wt % 7) * 32 + kjl;
        if (kj0 >= NTOK) continue;
        float acc[4][4];
        #pragma unroll
        for (int i = 0; i < 4; i++)
            #pragma unroll
            for (int j = 0; j < 4; j++) acc[i][j] = 0.f;
        const float* qp = sq + qi0 * 33;
        const float* kp = sk + kj0 * 33;
        #pragma unroll 8
        for (int kkk = 0; kkk < KD; kkk++) {
            float a0 = qp[kkk], a1 = qp[33 + kkk], a2 = qp[66 + kkk], a3 = qp[99 + kkk];
            float b0 = kp[kkk], b1 = kp[33 + kkk], b2 = kp[66 + kkk], b3 = kp[99 + kkk];
            acc[0][0] += a0 * b0; acc[0][1] += a0 * b1; acc[0][2] += a0 * b2; acc[0][3] += a0 * b3;
            acc[1][0] += a1 * b0; acc[1][1] += a1 * b1; acc[1][2] += a1 * b2; acc[1][3] += a1 * b3;
            acc[2][0] += a2 * b0; acc[2][1] += a2 * b1; acc[2][2] += a2 * b2; acc[2][3] += a2 * b3;
            acc[3][0] += a3 * b0; acc[3][1] += a3 * b1; acc[3][2] += a3 * b2; acc[3][3] += a3 * b3;
        }
        float* sp = sS + qi0 * 197 + kj0;
        #pragma unroll
        for (int i = 0; i < 4; i++)
            #pragma unroll
            for (int j = 0; j < 4; j++)
                sp[i * 197 + j] = acc[i][j];
    }
    __syncthreads();

    // ---- softmax rows (scale + bias gather, max, exp, normalize) ----
    const float* bh = biases + h * n_off;
    for (int r = wid; r < QT; r += 8) {
        const int* ip = bidx + (size_t)(qt * QT + r) * NTOK;
        float* srow = sS + r * 197;
        float mx = -3.0e38f;
        for (int c = lane; c < NTOK; c += 32) {
            float v = srow[c] * SCALE + __ldg(bh + __ldg(ip + c));
            srow[c] = v;
            mx = fmaxf(mx, v);
        }
        #pragma unroll
        for (int o = 16; o; o >>= 1) mx = fmaxf(mx, __shfl_xor_sync(0xffffffffu, mx, o));
        float sum = 0.f;
        for (int c = lane; c < NTOK; c += 32) {
            float e = __expf(srow[c] - mx);
            srow[c] = e;
            sum += e;
        }
        #pragma unroll
        for (int o = 16; o; o >>= 1) sum += __shfl_xor_sync(0xffffffffu, sum, o);
        float inv = 1.f / sum;
        for (int c = lane; c < NTOK; c += 32) srow[c] *= inv;
    }
    __syncthreads();

    // ---- O = P V : warp owns row-groups g=wid and g=wid+8 (rows g*4..g*4+3),
    //      lane owns 4 consecutive output cols. V streamed in 4 tiles of 49. ----
    float acc0[4][4], acc1[4][4];
    #pragma unroll
    for (int i = 0; i < 4; i++)
        #pragma unroll
        for (int j = 0; j < 4; j++) { acc0[i][j] = 0.f; acc1[i][j] = 0.f; }
    const int g2ok = (wid + 8) < 13;
    const int c0 = lane << 2;

    for (int vt = 0; vt < 4; vt++) {
        if (vt) __syncthreads();
        for (int i = tid; i < QT * 32; i += 256) {
            int r = i >> 5, c = (i & 31) << 2;
            float4 v = *(const float4*)(base + (size_t)(vt * QT + r) * HQKV + 2 * KD + c);
            *(float4*)(sv + r * 128 + c) = v;
        }
        __syncthreads();
        const float* s1 = sS + (wid * 4) * 197 + vt * QT;
        const float* s2 = sS + ((wid + 8) * 4) * 197 + vt * QT;
        #pragma unroll 7
        for (int m = 0; m < QT; m++) {
            float4 vv = *(const float4*)(sv + m * 128 + c0);
            float p0 = s1[m], p1 = s1[197 + m], p2 = s1[394 + m], p3 = s1[591 + m];
            acc0[0][0] += p0 * vv.x; acc0[0][1] += p0 * vv.y; acc0[0][2] += p0 * vv.z; acc0[0][3] += p0 * vv.w;
            acc0[1][0] += p1 * vv.x; acc0[1][1] += p1 * vv.y; acc0[1][2] += p1 * vv.z; acc0[1][3] += p1 * vv.w;
            acc0[2][0] += p2 * vv.x; acc0[2][1] += p2 * vv.y; acc0[2][2] += p2 * vv.z; acc0[2][3] += p2 * vv.w;
            acc0[3][0] += p3 * vv.x; acc0[3][1] += p3 * vv.y; acc0[3][2] += p3 * vv.z; acc0[3][3] += p3 * vv.w;
            if (g2ok) {
                float q0 = s2[m], q1 = s2[197 + m], q2 = s2[394 + m], q3 = s2[591 + m];
                acc1[0][0] += q0 * vv.x; acc1[0][1] += q0 * vv.y; acc1[0][2] += q0 * vv.z; acc1[0][3] += q0 * vv.w;
                acc1[1][0] += q1 * vv.x; acc1[1][1] += q1 * vv.y; acc1[1][2] += q1 * vv.z; acc1[1][3] += q1 * vv.w;
                acc1[2][0] += q2 * vv.x; acc1[2][1] += q2 * vv.y; acc1[2][2] += q2 * vv.z; acc1[2][3] += q2 * vv.w;
                acc1[3][0] += q3 * vv.x; acc1[3][1] += q3 * vv.y; acc1[3][2] += q3 * vv.z; acc1[3][3] += q3 * vv.w;
            }
        }
    }

    const size_t obase = ((size_t)b * NTOK + (size_t)qt * QT) * DH + h * DV + c0;
    #pragma unroll
    for (int i = 0; i < 4; i++) {
        int r = wid * 4 + i;  // 0..31, always valid
        *(float4*)(attn_out + obase + (size_t)r * DH) =
            make_float4(acc0[i][0], acc0[i][1], acc0[i][2], acc0[i][3]);
    }
    if (g2ok) {
        #pragma unroll
        for (int i = 0; i < 4; i++) {
            int r = (wid + 8) * 4 + i;  // 32..51
            if (r < QT)
                *(float4*)(attn_out + obase + (size_t)r * DH) =
                    make_float4(acc1[i][0], acc1[i][1], acc1[i][2], acc1[i][3]);
        }
    }
}

// ---------------------------------------------------------------------------
extern "C" void kernel_launch(void* const* d_in, const int* in_sizes, int n_in,
                              void* d_out, int out_size)
{
    const float* x      = (const float*)d_in[0];
    const float* qkv_w  = (const float*)d_in[1];
    const float* qkv_b  = (const float*)d_in[2];
    const float* proj_w = (const float*)d_in[3];
    const float* proj_b = (const float*)d_in[4];
    const float* ab     = (const float*)d_in[5];
    const int*   bidx   = (const int*)d_in[6];
    float* out = (float*)d_out;
    const int n_off = in_sizes[5] / NH;

    float *qkv_buf, *att_buf;
    cudaGetSymbolAddress((void**)&qkv_buf, g_qkv);
    cudaGetSymbolAddress((void**)&att_buf, g_att);

    cudaFuncSetAttribute(attn_kernel, cudaFuncAttributeMaxDynamicSharedMemorySize,
                         27460 * (int)sizeof(float));

    const int M = B_SZ * NTOK;  // 50176

    // 1) QKV = x @ qkv_w^T + qkv_b
    gemm_tn_bias<<<dim3(HQKV / 128, M / 128), 256>>>(x, qkv_w, qkv_b, qkv_buf,
                                                     M, HQKV, C_DIM);
    // 2) attention per (qtile, head, batch)
    attn_kernel<<<dim3(4, NH, B_SZ), 256, 27460 * sizeof(float)>>>(
        qkv_buf, ab, bidx, att_buf, n_off);
    // 3) out = att @ proj_w^T + proj_b
    gemm_tn_bias<<<dim3(C_DIM / 128, M / 128), 256>>>(att_buf, proj_w, proj_b, out,
                                                      M, C_DIM, DH);
}

// round 2
// speedup vs baseline: 1.7574x; 1.7574x over previous
#include <cuda_runtime.h>
#include <cstdint>
#include <cstddef>

#define B_SZ 256
#define NTOK 196
#define C_DIM 512
#define NH 8
#define KD 32
#define DV 128
#define DH 1024
#define HQKV 1536
#define QT 49
#define SCALE 0.17677669529663687f

// Scratch buffers (device globals: allocation-free rule)
__device__ float g_qkv[(size_t)B_SZ * NTOK * HQKV];   // [B, N, 1536]
__device__ float g_att[(size_t)B_SZ * NTOK * DH];     // [B, N, 1024]

__device__ __forceinline__ uint32_t f2tf32(float x) {
    uint32_t r;
    asm("cvt.rna.tf32.f32 %0, %1;" : "=r"(r) : "f"(x));
    return r;
}

__device__ __forceinline__ void mma_tf32(float* d, const uint32_t* a, const uint32_t* b) {
    asm volatile(
        "mma.sync.aligned.m16n8k8.row.col.f32.tf32.tf32.f32 "
        "{%0,%1,%2,%3}, {%4,%5,%6,%7}, {%8,%9}, {%0,%1,%2,%3};\n"
        : "+f"(d[0]), "+f"(d[1]), "+f"(d[2]), "+f"(d[3])
        : "r"(a[0]), "r"(a[1]), "r"(a[2]), "r"(a[3]),
          "r"(b[0]), "r"(b[1]));
}

// ---------------------------------------------------------------------------
// C[M,N] = A[M,K] @ W[N,K]^T + bias[N]  via tf32 mma.sync.
// 128x128 block tile, BK=32, 8 warps in 2x4 grid (64x32 warp tile).
// Smem pitch 36 (== 4 mod 32) makes fragment LDS conflict-free.
// M%128==0, N%128==0, K%32==0 hold for both call sites.
// ---------------------------------------------------------------------------
__global__ void __launch_bounds__(256, 2)
gemm_tf32_bias(const float* __restrict__ A, const float* __restrict__ W,
               const float* __restrict__ bias, float* __restrict__ C,
               int M, int N, int K)
{
    __shared__ uint32_t As[128 * 36];   // [m][k] tf32 bits, pitch 36
    __shared__ uint32_t Bs[128 * 36];   // [n][k] tf32 bits

    const int tid  = threadIdx.x;
    const int lane = tid & 31;
    const int wid  = tid >> 5;
    const int warpM = wid >> 2;          // 0..1
    const int warpN = wid & 3;           // 0..3
    const int g = lane >> 2;             // 0..7
    const int c = lane & 3;              // 0..3
    const int m0 = blockIdx.y * 128;
    const int n0 = blockIdx.x * 128;

    float acc[4][4][4];
    #pragma unroll
    for (int mt = 0; mt < 4; mt++)
        #pragma unroll
        for (int nt = 0; nt < 4; nt++)
            #pragma unroll
            for (int e = 0; e < 4; e++) acc[mt][nt][e] = 0.f;

    for (int kk = 0; kk < K; kk += 32) {
        // ---- stage global -> smem (with tf32 rounding) ----
        #pragma unroll
        for (int it = 0; it < 4; it++) {
            int idx = tid + it * 256;        // 0..1023
            int row = idx >> 3;              // 0..127
            int col = (idx & 7) << 2;        // 0,4,..,28
            float4 av = *(const float4*)(A + (size_t)(m0 + row) * K + kk + col);
            float4 wv = *(const float4*)(W + (size_t)(n0 + row) * K + kk + col);
            uint32_t* ap = As + row * 36 + col;
            ap[0] = f2tf32(av.x); ap[1] = f2tf32(av.y);
            ap[2] = f2tf32(av.z); ap[3] = f2tf32(av.w);
            uint32_t* bp = Bs + row * 36 + col;
            bp[0] = f2tf32(wv.x); bp[1] = f2tf32(wv.y);
            bp[2] = f2tf32(wv.z); bp[3] = f2tf32(wv.w);
        }
        __syncthreads();

        // ---- 4 mma k-steps ----
        #pragma unroll
        for (int ks = 0; ks < 4; ks++) {
            const int kb = ks * 8;
            uint32_t af[4][4], bf[4][2];
            #pragma unroll
            for (int mt = 0; mt < 4; mt++) {
                int rb = warpM * 64 + mt * 16;
                const uint32_t* p0 = As + (rb + g) * 36 + kb + c;
                const uint32_t* p1 = As + (rb + g + 8) * 36 + kb + c;
                af[mt][0] = p0[0];
                af[mt][1] = p1[0];
                af[mt][2] = p0[4];
                af[mt][3] = p1[4];
            }
            #pragma unroll
            for (int nt = 0; nt < 4; nt++) {
                int nb = warpN * 32 + nt * 8;
                const uint32_t* p = Bs + (nb + g) * 36 + kb + c;
                bf[nt][0] = p[0];
                bf[nt][1] = p[4];
            }
            #pragma unroll
            for (int mt = 0; mt < 4; mt++)
                #pragma unroll
                for (int nt = 0; nt < 4; nt++)
                    mma_tf32(acc[mt][nt], af[mt], bf[nt]);
        }
        __syncthreads();
    }

    // ---- epilogue: bias + store ----
    #pragma unroll
    for (int mt = 0; mt < 4; mt++) {
        int r0 = m0 + warpM * 64 + mt * 16 + g;
        #pragma unroll
        for (int nt = 0; nt < 4; nt++) {
            int col = n0 + warpN * 32 + nt * 8 + 2 * c;
            float b0 = bias[col], b1 = bias[col + 1];
            float* cp0 = C + (size_t)r0 * N + col;
            float* cp1 = C + (size_t)(r0 + 8) * N + col;
            *(float2*)cp0 = make_float2(acc[mt][nt][0] + b0, acc[mt][nt][1] + b1);
            *(float2*)cp1 = make_float2(acc[mt][nt][2] + b0, acc[mt][nt][3] + b1);
        }
    }
}

// ---------------------------------------------------------------------------
// Attention: one CTA per (qtile of 49 queries, head, batch). 256 threads.
// S = qK^T (smem), softmax(S*scale + bias) in-place, O = P V.
// ---------------------------------------------------------------------------
__global__ void __launch_bounds__(256)
attn_kernel(const float* __restrict__ qkv, const float* __restrict__ biases,
            const int* __restrict__ bidx, float* __restrict__ attn_out, int n_off)
{
    extern __shared__ float sm[];
    float* sq = sm;                 // [64][33]  = 2112 floats (rows 49..63 zero)
    float* sk = sm + 2112;          // [196][33] = 6468
    float* sS = sm + 8580;          // [64][197] = 12608
    float* sv = sm + 21188;         // [49][128] = 6272   (total 27460 floats)

    const int tid  = threadIdx.x;
    const int lane = tid & 31;
    const int wid  = tid >> 5;
    const int qt = blockIdx.x;
    const int h  = blockIdx.y;
    const int b  = blockIdx.z;
    const float* base = qkv + (size_t)b * NTOK * HQKV + h * (2 * KD + DV);

    // ---- load Q tile [49][32] ----
    for (int i = tid; i < QT * 8; i += 256) {
        int r = i >> 3, c = (i & 7) << 2;
        float4 v = *(const float4*)(base + (size_t)(qt * QT + r) * HQKV + c);
        float* d = sq + r * 33 + c;
        d[0] = v.x; d[1] = v.y; d[2] = v.z; d[3] = v.w;
    }
    for (int i = tid; i < 15 * 33; i += 256) sq[49 * 33 + i] = 0.f;
    // ---- load K [196][32] ----
    for (int i = tid; i < NTOK * 8; i += 256) {
        int r = i >> 3, c = (i & 7) << 2;
        float4 v = *(const float4*)(base + (size_t)r * HQKV + KD + c);
        float* d = sk + r * 33 + c;
        d[0] = v.x; d[1] = v.y; d[2] = v.z; d[3] = v.w;
    }
    __syncthreads();

    // ---- S = q K^T : warp tiles 16x32, lane microtile 4x4 ----
    const int qil = (lane & 3) << 2;   // 0,4,8,12
    const int kjl = (lane >> 2) << 2;  // 0..28
    for (int wt = wid; wt < 28; wt += 8) {
        int qi0 = (wt / 7) * 16 + qil;
        int kj0 = (wt % 7) * 32 + kjl;
        if (kj0 >= NTOK) continue;
        float acc[4][4];
        #pragma unroll
        for (int i = 0; i < 4; i++)
            #pragma unroll
            for (int j = 0; j < 4; j++) acc[i][j] = 0.f;
        const float* qp = sq + qi0 * 33;
        const float* kp = sk + kj0 * 33;
        #pragma unroll 8
        for (int kkk = 0; kkk < KD; kkk++) {
            float a0 = qp[kkk], a1 = qp[33 + kkk], a2 = qp[66 + kkk], a3 = qp[99 + kkk];
            float b0 = kp[kkk], b1 = kp[33 + kkk], b2 = kp[66 + kkk], b3 = kp[99 + kkk];
            acc[0][0] += a0 * b0; acc[0][1] += a0 * b1; acc[0][2] += a0 * b2; acc[0][3] += a0 * b3;
            acc[1][0] += a1 * b0; acc[1][1] += a1 * b1; acc[1][2] += a1 * b2; acc[1][3] += a1 * b3;
            acc[2][0] += a2 * b0; acc[2][1] += a2 * b1; acc[2][2] += a2 * b2; acc[2][3] += a2 * b3;
            acc[3][0] += a3 * b0; acc[3][1] += a3 * b1; acc[3][2] += a3 * b2; acc[3][3] += a3 * b3;
        }
        float* sp = sS + qi0 * 197 + kj0;
        #pragma unroll
        for (int i = 0; i < 4; i++)
            #pragma unroll
            for (int j = 0; j < 4; j++)
                sp[i * 197 + j] = acc[i][j];
    }
    __syncthreads();

    // ---- softmax rows (scale + bias gather, max, exp, normalize) ----
    const float* bh = biases + h * n_off;
    for (int r = wid; r < QT; r += 8) {
        const int* ip = bidx + (size_t)(qt * QT + r) * NTOK;
        float* srow = sS + r * 197;
        float mx = -3.0e38f;
        for (int c = lane; c < NTOK; c += 32) {
            float v = srow[c] * SCALE + __ldg(bh + __ldg(ip + c));
            srow[c] = v;
            mx = fmaxf(mx, v);
        }
        #pragma unroll
        for (int o = 16; o; o >>= 1) mx = fmaxf(mx, __shfl_xor_sync(0xffffffffu, mx, o));
        float sum = 0.f;
        for (int c = lane; c < NTOK; c += 32) {
            float e = __expf(srow[c] - mx);
            srow[c] = e;
            sum += e;
        }
        #pragma unroll
        for (int o = 16; o; o >>= 1) sum += __shfl_xor_sync(0xffffffffu, sum, o);
        float inv = 1.f / sum;
        for (int c = lane; c < NTOK; c += 32) srow[c] *= inv;
    }
    __syncthreads();

    // ---- O = P V ----
    float acc0[4][4], acc1[4][4];
    #pragma unroll
    for (int i = 0; i < 4; i++)
        #pragma unroll
        for (int j = 0; j < 4; j++) { acc0[i][j] = 0.f; acc1[i][j] = 0.f; }
    const int g2ok = (wid + 8) < 13;
    const int c0 = lane << 2;

    for (int vt = 0; vt < 4; vt++) {
        if (vt) __syncthreads();
        for (int i = tid; i < QT * 32; i += 256) {
            int r = i >> 5, c = (i & 31) << 2;
            float4 v = *(const float4*)(base + (size_t)(vt * QT + r) * HQKV + 2 * KD + c);
            *(float4*)(sv + r * 128 + c) = v;
        }
        __syncthreads();
        const float* s1 = sS + (wid * 4) * 197 + vt * QT;
        const float* s2 = sS + ((wid + 8) * 4) * 197 + vt * QT;
        #pragma unroll 7
        for (int m = 0; m < QT; m++) {
            float4 vv = *(const float4*)(sv + m * 128 + c0);
            float p0 = s1[m], p1 = s1[197 + m], p2 = s1[394 + m], p3 = s1[591 + m];
            acc0[0][0] += p0 * vv.x; acc0[0][1] += p0 * vv.y; acc0[0][2] += p0 * vv.z; acc0[0][3] += p0 * vv.w;
            acc0[1][0] += p1 * vv.x; acc0[1][1] += p1 * vv.y; acc0[1][2] += p1 * vv.z; acc0[1][3] += p1 * vv.w;
            acc0[2][0] += p2 * vv.x; acc0[2][1] += p2 * vv.y; acc0[2][2] += p2 * vv.z; acc0[2][3] += p2 * vv.w;
            acc0[3][0] += p3 * vv.x; acc0[3][1] += p3 * vv.y; acc0[3][2] += p3 * vv.z; acc0[3][3] += p3 * vv.w;
            if (g2ok) {
                float q0 = s2[m], q1 = s2[197 + m], q2 = s2[394 + m], q3 = s2[591 + m];
                acc1[0][0] += q0 * vv.x; acc1[0][1] += q0 * vv.y; acc1[0][2] += q0 * vv.z; acc1[0][3] += q0 * vv.w;
                acc1[1][0] += q1 * vv.x; acc1[1][1] += q1 * vv.y; acc1[1][2] += q1 * vv.z; acc1[1][3] += q1 * vv.w;
                acc1[2][0] += q2 * vv.x; acc1[2][1] += q2 * vv.y; acc1[2][2] += q2 * vv.z; acc1[2][3] += q2 * vv.w;
                acc1[3][0] += q3 * vv.x; acc1[3][1] += q3 * vv.y; acc1[3][2] += q3 * vv.z; acc1[3][3] += q3 * vv.w;
            }
        }
    }

    const size_t obase = ((size_t)b * NTOK + (size_t)qt * QT) * DH + h * DV + c0;
    #pragma unroll
    for (int i = 0; i < 4; i++) {
        int r = wid * 4 + i;
        *(float4*)(attn_out + obase + (size_t)r * DH) =
            make_float4(acc0[i][0], acc0[i][1], acc0[i][2], acc0[i][3]);
    }
    if (g2ok) {
        #pragma unroll
        for (int i = 0; i < 4; i++) {
            int r = (wid + 8) * 4 + i;
            if (r < QT)
                *(float4*)(attn_out + obase + (size_t)r * DH) =
                    make_float4(acc1[i][0], acc1[i][1], acc1[i][2], acc1[i][3]);
        }
    }
}

// ---------------------------------------------------------------------------
extern "C" void kernel_launch(void* const* d_in, const int* in_sizes, int n_in,
                              void* d_out, int out_size)
{
    const float* x      = (const float*)d_in[0];
    const float* qkv_w  = (const float*)d_in[1];
    const float* qkv_b  = (const float*)d_in[2];
    const float* proj_w = (const float*)d_in[3];
    const float* proj_b = (const float*)d_in[4];
    const float* ab     = (const float*)d_in[5];
    const int*   bidx   = (const int*)d_in[6];
    float* out = (float*)d_out;
    const int n_off = in_sizes[5] / NH;

    float *qkv_buf, *att_buf;
    cudaGetSymbolAddress((void**)&qkv_buf, g_qkv);
    cudaGetSymbolAddress((void**)&att_buf, g_att);

    cudaFuncSetAttribute(attn_kernel, cudaFuncAttributeMaxDynamicSharedMemorySize,
                         27460 * (int)sizeof(float));

    const int M = B_SZ * NTOK;  // 50176

    // 1) QKV = x @ qkv_w^T + qkv_b   (tf32 tensor-core GEMM)
    gemm_tf32_bias<<<dim3(HQKV / 128, M / 128), 256>>>(x, qkv_w, qkv_b, qkv_buf,
                                                       M, HQKV, C_DIM);
    // 2) attention per (qtile, head, batch)
    attn_kernel<<<dim3(4, NH, B_SZ), 256, 27460 * sizeof(float)>>>(
        qkv_buf, ab, bidx, att_buf, n_off);
    // 3) out = att @ proj_w^T + proj_b
    gemm_tf32_bias<<<dim3(C_DIM / 128, M / 128), 256>>>(att_buf, proj_w, proj_b, out,
                                                        M, C_DIM, DH);
}

// round 3
// speedup vs baseline: 2.5564x; 1.4547x over previous
#include <cuda_runtime.h>
#include <cstdint>
#include <cstddef>

#define B_SZ 256
#define NTOK 196
#define C_DIM 512
#define NH 8
#define KD 32
#define DV 128
#define DH 1024
#define HQKV 1536
#define QT 49
#define SCALE 0.17677669529663687f

// padded attention dims
#define MP 64          // padded query rows
#define NP 224         // padded key count (4 chunks of 56)
#define CH 56          // PV k-chunk
#define PS 228         // sS pitch (fp32)  : 228 % 32 == 4  -> 4g+c conflict-free
#define PQ 36          // sq/sk pitch (u32): 36 % 32  == 4  -> 4g+c conflict-free
#define PVP 136        // sv pitch (u32)   : 136 % 32 == 8  -> 8c+g conflict-free

// Scratch buffers (device globals: allocation-free rule)
__device__ float g_qkv[(size_t)B_SZ * NTOK * HQKV];     // [B, N, 1536]
__device__ float g_att[(size_t)B_SZ * NTOK * DH];       // [B, N, 1024]
__device__ float g_bmat[(size_t)NH * NTOK * NTOK];      // [8, 196, 196]

__device__ __forceinline__ uint32_t f2tf32(float x) {
    uint32_t r;
    asm("cvt.rna.tf32.f32 %0, %1;" : "=r"(r) : "f"(x));
    return r;
}

__device__ __forceinline__ void mma_tf32(float* d, const uint32_t* a, const uint32_t* b) {
    asm volatile(
        "mma.sync.aligned.m16n8k8.row.col.f32.tf32.tf32.f32 "
        "{%0,%1,%2,%3}, {%4,%5,%6,%7}, {%8,%9}, {%0,%1,%2,%3};\n"
        : "+f"(d[0]), "+f"(d[1]), "+f"(d[2]), "+f"(d[3])
        : "r"(a[0]), "r"(a[1]), "r"(a[2]), "r"(a[3]),
          "r"(b[0]), "r"(b[1]));
}

// ---------------------------------------------------------------------------
// bmat[h][i][j] = attention_biases[h][bias_idxs[i][j]]
// ---------------------------------------------------------------------------
__global__ void bias_precompute(const float* __restrict__ ab,
                                const int* __restrict__ bidx,
                                float* __restrict__ bmat, int n_off)
{
    int idx = blockIdx.x * 256 + threadIdx.x;
    if (idx >= NH * NTOK * NTOK) return;
    int h  = idx / (NTOK * NTOK);
    int ij = idx % (NTOK * NTOK);
    bmat[idx] = ab[h * n_off + bidx[ij]];
}

// ---------------------------------------------------------------------------
// C[M,N] = A[M,K] @ W[N,K]^T + bias[N]  via tf32 mma.sync. (unchanged R2)
// ---------------------------------------------------------------------------
__global__ void __launch_bounds__(256, 2)
gemm_tf32_bias(const float* __restrict__ A, const float* __restrict__ W,
               const float* __restrict__ bias, float* __restrict__ C,
               int M, int N, int K)
{
    __shared__ uint32_t As[128 * 36];
    __shared__ uint32_t Bs[128 * 36];

    const int tid  = threadIdx.x;
    const int lane = tid & 31;
    const int wid  = tid >> 5;
    const int warpM = wid >> 2;
    const int warpN = wid & 3;
    const int g = lane >> 2;
    const int c = lane & 3;
    const int m0 = blockIdx.y * 128;
    const int n0 = blockIdx.x * 128;

    float acc[4][4][4];
    #pragma unroll
    for (int mt = 0; mt < 4; mt++)
        #pragma unroll
        for (int nt = 0; nt < 4; nt++)
            #pragma unroll
            for (int e = 0; e < 4; e++) acc[mt][nt][e] = 0.f;

    for (int kk = 0; kk < K; kk += 32) {
        #pragma unroll
        for (int it = 0; it < 4; it++) {
            int idx = tid + it * 256;
            int row = idx >> 3;
            int col = (idx & 7) << 2;
            float4 av = *(const float4*)(A + (size_t)(m0 + row) * K + kk + col);
            float4 wv = *(const float4*)(W + (size_t)(n0 + row) * K + kk + col);
            uint32_t* ap = As + row * 36 + col;
            ap[0] = f2tf32(av.x); ap[1] = f2tf32(av.y);
            ap[2] = f2tf32(av.z); ap[3] = f2tf32(av.w);
            uint32_t* bp = Bs + row * 36 + col;
            bp[0] = f2tf32(wv.x); bp[1] = f2tf32(wv.y);
            bp[2] = f2tf32(wv.z); bp[3] = f2tf32(wv.w);
        }
        __syncthreads();

        #pragma unroll
        for (int ks = 0; ks < 4; ks++) {
            const int kb = ks * 8;
            uint32_t af[4][4], bf[4][2];
            #pragma unroll
            for (int mt = 0; mt < 4; mt++) {
                int rb = warpM * 64 + mt * 16;
                const uint32_t* p0 = As + (rb + g) * 36 + kb + c;
                const uint32_t* p1 = As + (rb + g + 8) * 36 + kb + c;
                af[mt][0] = p0[0];
                af[mt][1] = p1[0];
                af[mt][2] = p0[4];
                af[mt][3] = p1[4];
            }
            #pragma unroll
            for (int nt = 0; nt < 4; nt++) {
                int nb = warpN * 32 + nt * 8;
                const uint32_t* p = Bs + (nb + g) * 36 + kb + c;
                bf[nt][0] = p[0];
                bf[nt][1] = p[4];
            }
            #pragma unroll
            for (int mt = 0; mt < 4; mt++)
                #pragma unroll
                for (int nt = 0; nt < 4; nt++)
                    mma_tf32(acc[mt][nt], af[mt], bf[nt]);
        }
        __syncthreads();
    }

    #pragma unroll
    for (int mt = 0; mt < 4; mt++) {
        int r0 = m0 + warpM * 64 + mt * 16 + g;
        #pragma unroll
        for (int nt = 0; nt < 4; nt++) {
            int col = n0 + warpN * 32 + nt * 8 + 2 * c;
            float b0 = bias[col], b1 = bias[col + 1];
            float* cp0 = C + (size_t)r0 * N + col;
            float* cp1 = C + (size_t)(r0 + 8) * N + col;
            *(float2*)cp0 = make_float2(acc[mt][nt][0] + b0, acc[mt][nt][1] + b1);
            *(float2*)cp1 = make_float2(acc[mt][nt][2] + b0, acc[mt][nt][3] + b1);
        }
    }
}

// ---------------------------------------------------------------------------
// Tensor-core attention. One CTA per (qtile, head, batch). 256 threads.
// S = Q K^T via tf32 mma (M=64, N=224, K=32), softmax(+precomputed bias),
// O = P V via tf32 mma (M=64, N=128, K=224 in 4 chunks of 56).
// smem: sS[64][228] fp32 | sq[64][36] | sk[224][36]; sv[56][136] aliases sq.
// ---------------------------------------------------------------------------
__global__ void __launch_bounds__(256, 2)
attn_mma(const float* __restrict__ qkv, const float* __restrict__ bmat,
         float* __restrict__ attn_out)
{
    extern __shared__ uint32_t smu[];
    float*    sS = (float*)smu;                  // 64*228 = 14592
    uint32_t* sq = smu + MP * PS;                // 64*36  = 2304
    uint32_t* sk = sq + MP * PQ;                 // 224*36 = 8064
    uint32_t* sv = sq;                           // alias: 56*136 = 7616 <= 10368

    const int tid  = threadIdx.x;
    const int lane = tid & 31;
    const int wid  = tid >> 5;
    const int g = lane >> 2;
    const int c = lane & 3;
    const int warpM = wid >> 1;     // 0..3 -> 16 rows each
    const int warpN = wid & 1;      // 0..1
    const int qt = blockIdx.x;
    const int h  = blockIdx.y;
    const int b  = blockIdx.z;
    const float* base = qkv + (size_t)b * NTOK * HQKV + h * (2 * KD + DV);

    // ---- stage Q [64][32] (rows >=49 zero) and K [224][32] (rows >=196 zero)
    #pragma unroll
    for (int it = 0; it < 2; it++) {
        int i = tid + it * 256;              // 512 float4 slots
        int r = i >> 3, cc = (i & 7) << 2;
        uint32_t* d = sq + r * PQ + cc;
        if (r < QT) {
            float4 v = *(const float4*)(base + (size_t)(qt * QT + r) * HQKV + cc);
            d[0] = f2tf32(v.x); d[1] = f2tf32(v.y); d[2] = f2tf32(v.z); d[3] = f2tf32(v.w);
        } else { d[0] = 0u; d[1] = 0u; d[2] = 0u; d[3] = 0u; }
    }
    #pragma unroll
    for (int it = 0; it < 7; it++) {
        int i = tid + it * 256;              // 1792 float4 slots
        int r = i >> 3, cc = (i & 7) << 2;
        uint32_t* d = sk + r * PQ + cc;
        if (r < NTOK) {
            float4 v = *(const float4*)(base + (size_t)r * HQKV + KD + cc);
            d[0] = f2tf32(v.x); d[1] = f2tf32(v.y); d[2] = f2tf32(v.z); d[3] = f2tf32(v.w);
        } else { d[0] = 0u; d[1] = 0u; d[2] = 0u; d[3] = 0u; }
    }
    __syncthreads();

    // ---- S = Q K^T : warp tile 16 x 112 (14 n-tiles), 4 k-steps ----
    {
        float accS[14][4];
        #pragma unroll
        for (int nt = 0; nt < 14; nt++)
            #pragma unroll
            for (int e = 0; e < 4; e++) accS[nt][e] = 0.f;

        const int m0 = warpM * 16;
        #pragma unroll
        for (int ks = 0; ks < 4; ks++) {
            const int kb = ks * 8;
            uint32_t a[4];
            const uint32_t* p0 = sq + (m0 + g) * PQ + kb + c;
            const uint32_t* p1 = sq + (m0 + g + 8) * PQ + kb + c;
            a[0] = p0[0]; a[1] = p1[0]; a[2] = p0[4]; a[3] = p1[4];
            #pragma unroll
            for (int nt = 0; nt < 14; nt++) {
                int nb = warpN * 112 + nt * 8;
                const uint32_t* p = sk + (nb + g) * PQ + kb + c;
                uint32_t bfr[2] = {p[0], p[4]};
                mma_tf32(accS[nt], a, bfr);
            }
        }
        #pragma unroll
        for (int nt = 0; nt < 14; nt++) {
            int row = m0 + g;
            int col = warpN * 112 + nt * 8 + 2 * c;
            *(float2*)(sS + row * PS + col) = make_float2(accS[nt][0], accS[nt][1]);
            *(float2*)(sS + (row + 8) * PS + col) = make_float2(accS[nt][2], accS[nt][3]);
        }
    }
    __syncthreads();

    // ---- softmax rows 0..48, cols 0..195 (bias precomputed, linear) ----
    for (int r = wid; r < QT; r += 8) {
        const float* brow = bmat + ((size_t)h * NTOK + qt * QT + r) * NTOK;
        float* srow = sS + r * PS;
        float mx = -3.0e38f;
        for (int cc = lane; cc < NTOK; cc += 32) {
            float v = srow[cc] * SCALE + brow[cc];
            srow[cc] = v;
            mx = fmaxf(mx, v);
        }
        #pragma unroll
        for (int o = 16; o; o >>= 1) mx = fmaxf(mx, __shfl_xor_sync(0xffffffffu, mx, o));
        float sum = 0.f;
        for (int cc = lane; cc < NTOK; cc += 32) {
            float e = __expf(srow[cc] - mx);
            srow[cc] = e;
            sum += e;
        }
        #pragma unroll
        for (int o = 16; o; o >>= 1) sum += __shfl_xor_sync(0xffffffffu, sum, o);
        float inv = 1.f / sum;
        for (int cc = lane; cc < NTOK; cc += 32) srow[cc] *= inv;
    }
    __syncthreads();

    // ---- O = P V : 4 chunks of 56 keys; warp tile 16 x 64 (8 n-tiles) ----
    float accO[8][4];
    #pragma unroll
    for (int nt = 0; nt < 8; nt++)
        #pragma unroll
        for (int e = 0; e < 4; e++) accO[nt][e] = 0.f;

    const int m0 = warpM * 16;
    for (int ch = 0; ch < 4; ch++) {
        // stage V chunk [56][128] transposed-free k-major, tf32, rows>=196 zero
        #pragma unroll
        for (int it = 0; it < 7; it++) {
            int i = tid + it * 256;          // 1792 float4 slots
            int r = i >> 5, cc = (i & 31) << 2;
            int gk = ch * CH + r;
            uint32_t* d = sv + r * PVP + cc;
            if (gk < NTOK) {
                float4 v = *(const float4*)(base + (size_t)gk * HQKV + 2 * KD + cc);
                d[0] = f2tf32(v.x); d[1] = f2tf32(v.y); d[2] = f2tf32(v.z); d[3] = f2tf32(v.w);
            } else { d[0] = 0u; d[1] = 0u; d[2] = 0u; d[3] = 0u; }
        }
        __syncthreads();

        #pragma unroll
        for (int ks = 0; ks < 7; ks++) {
            const int kl = ks * 8;
            const int kgl = ch * CH + kl;
            uint32_t a[4];
            const float* q0 = sS + (m0 + g) * PS + kgl + c;
            const float* q1 = sS + (m0 + g + 8) * PS + kgl + c;
            a[0] = f2tf32(q0[0]); a[1] = f2tf32(q1[0]);
            a[2] = f2tf32(q0[4]); a[3] = f2tf32(q1[4]);
            #pragma unroll
            for (int nt = 0; nt < 8; nt++) {
                int nb = warpN * 64 + nt * 8;
                uint32_t bfr[2];
                bfr[0] = sv[(kl + c) * PVP + nb + g];
                bfr[1] = sv[(kl + c + 4) * PVP + nb + g];
                mma_tf32(accO[nt], a, bfr);
            }
        }
        __syncthreads();
    }

    // ---- store O rows < 49 ----
    {
        int r1 = m0 + g;
        int r2 = r1 + 8;
        const size_t ob = ((size_t)b * NTOK + qt * QT) * DH + h * DV;
        #pragma unroll
        for (int nt = 0; nt < 8; nt++) {
            int col = warpN * 64 + nt * 8 + 2 * c;
            if (r1 < QT)
                *(float2*)(attn_out + ob + (size_t)r1 * DH + col) =
                    make_float2(accO[nt][0], accO[nt][1]);
            if (r2 < QT)
                *(float2*)(attn_out + ob + (size_t)r2 * DH + col) =
                    make_float2(accO[nt][2], accO[nt][3]);
        }
    }
}

// ---------------------------------------------------------------------------
extern "C" void kernel_launch(void* const* d_in, const int* in_sizes, int n_in,
                              void* d_out, int out_size)
{
    const float* x      = (const float*)d_in[0];
    const float* qkv_w  = (const float*)d_in[1];
    const float* qkv_b  = (const float*)d_in[2];
    const float* proj_w = (const float*)d_in[3];
    const float* proj_b = (const float*)d_in[4];
    const float* ab     = (const float*)d_in[5];
    const int*   bidx   = (const int*)d_in[6];
    float* out = (float*)d_out;
    const int n_off = in_sizes[5] / NH;

    float *qkv_buf, *att_buf, *bmat;
    cudaGetSymbolAddress((void**)&qkv_buf, g_qkv);
    cudaGetSymbolAddress((void**)&att_buf, g_att);
    cudaGetSymbolAddress((void**)&bmat, g_bmat);

    const int ATTN_SMEM = (MP * PS + MP * PQ + NP * PQ) * (int)sizeof(uint32_t); // 99840
    cudaFuncSetAttribute(attn_mma, cudaFuncAttributeMaxDynamicSharedMemorySize, ATTN_SMEM);

    const int M = B_SZ * NTOK;  // 50176

    // 0) bias matrix precompute (batch-invariant, tiny)
    bias_precompute<<<(NH * NTOK * NTOK + 255) / 256, 256>>>(ab, bidx, bmat, n_off);
    // 1) QKV = x @ qkv_w^T + qkv_b
    gemm_tf32_bias<<<dim3(HQKV / 128, M / 128), 256>>>(x, qkv_w, qkv_b, qkv_buf,
                                                       M, HQKV, C_DIM);
    // 2) attention
    attn_mma<<<dim3(4, NH, B_SZ), 256, ATTN_SMEM>>>(qkv_buf, bmat, att_buf);
    // 3) out = att @ proj_w^T + proj_b
    gemm_tf32_bias<<<dim3(C_DIM / 128, M / 128), 256>>>(att_buf, proj_w, proj_b, out,
                                                        M, C_DIM, DH);
}